// round 9
// baseline (speedup 1.0000x reference)
#include <cuda_runtime.h>
#include <cuda_bf16.h>
#include <math.h>
#include <stdint.h>

#define H_   48
#define W_   48
#define NP   2304        // H_*W_
#define NB   8
#define CIN  128
#define COUT 256
#define NK   9
#define HID  512
#define KC   1152        // NK*CIN
#define VS8  8
#define KT   128         // K chunk per kk slice

// GEMM tiling
#define GBM 128
#define GBN 128
#define GBK 32
#define GST 3            // pipeline stages
#define GRPF 36          // floats per smem row (32 + 4 pad)
#define GRPB 144         // bytes per smem row (mod 128 == 16 -> conflict-free ldmatrix)
#define STAGE_A (GBM * GRPB)             // 18432
#define STAGE_B (GBN * GRPB)             // 18432
#define STAGE_SZ (STAGE_A + STAGE_B)     // 36864
#define SM_TOTAL (GST * STAGE_SZ)        // 110592

// ---------------- scratch (static device globals; no allocation) ----------------
__device__ float  g_xt  [NB * NP * CIN];       // x transposed to [b][p][c]
__device__ float4 g_pk  [NP * NK];             // mean_h, mean_w, sigma
__device__ float  g_wts [NB * NP * NK * VS8];
__device__ int    g_lin [NB * NP * NK * VS8];
__device__ float  g_wub2[COUT * KC];           // Wu tf32-rounded, [n][k] contiguous
__device__ float  g_af  [NB * NP * KC];        // gathered A, tf32-rounded (85MB)

// ---------------- helpers ----------------
__device__ __forceinline__ uint32_t smem_u32(const void* p) {
    uint32_t a;
    asm("{ .reg .u64 t; cvta.to.shared.u64 t, %1; cvt.u32.u64 %0, t; }" : "=r"(a) : "l"(p));
    return a;
}
__device__ __forceinline__ void ldm_x4(uint32_t* r, uint32_t addr) {
    asm volatile("ldmatrix.sync.aligned.m8n8.x4.shared.b16 {%0,%1,%2,%3}, [%4];"
                 : "=r"(r[0]), "=r"(r[1]), "=r"(r[2]), "=r"(r[3]) : "r"(addr));
}
__device__ __forceinline__ void mma_tf32(float* d, const uint32_t* a, const uint32_t* b) {
    asm volatile("mma.sync.aligned.m16n8k8.row.col.f32.tf32.tf32.f32 "
                 "{%0,%1,%2,%3}, {%4,%5,%6,%7}, {%8,%9}, {%0,%1,%2,%3};"
                 : "+f"(d[0]), "+f"(d[1]), "+f"(d[2]), "+f"(d[3])
                 : "r"(a[0]), "r"(a[1]), "r"(a[2]), "r"(a[3]), "r"(b[0]), "r"(b[1]));
}
__device__ __forceinline__ uint32_t f2tf32(float f) {
    uint32_t o;
    asm("cvt.rna.tf32.f32 %0, %1;" : "=r"(o) : "f"(f));
    return o;
}
__device__ __forceinline__ void cp_async16(uint32_t dst, const void* src) {
    asm volatile("cp.async.cg.shared.global [%0], [%1], 16;" :: "r"(dst), "l"(src) : "memory");
}
__device__ __forceinline__ void cp_commit() {
    asm volatile("cp.async.commit_group;" ::: "memory");
}

// ---------------- kernel 0a: transpose x (b,c,p) -> (b,p,c) ----------------
__global__ void transpose_x_kernel(const float* __restrict__ in) {
    __shared__ float tile[32][33];
    int b = blockIdx.z;
    const float* inb = in + (size_t)b * CIN * NP;
    float* outb = g_xt + (size_t)b * NP * CIN;
    int c0 = blockIdx.x * 32;
    int r0 = blockIdx.y * 32;
    int tx = threadIdx.x, ty = threadIdx.y;
#pragma unroll
    for (int q = 0; q < 32; q += 8)
        tile[ty + q][tx] = inb[(r0 + ty + q) * NP + c0 + tx];
    __syncthreads();
#pragma unroll
    for (int q = 0; q < 32; q += 8)
        outb[(size_t)(c0 + ty + q) * CIN + r0 + tx] = tile[tx][ty + q];
}

// ---------------- kernel 0b: Wu -> tf32-rounded fp32, [n][k] contiguous ----------------
__global__ void wu_prep_kernel(const float* __restrict__ wu) {
    int t = blockIdx.x * 256 + threadIdx.x;      // COUT*KC/4 = 73728
    if (t >= COUT * KC / 4) return;
    float4 v = ((const float4*)wu)[t];
    uint4 o;
    o.x = f2tf32(v.x); o.y = f2tf32(v.y); o.z = f2tf32(v.z); o.w = f2tf32(v.w);
    ((uint4*)g_wub2)[t] = o;
}

// ---------------- kernel 1: per-pixel MLP -> means / sigma ----------------
__global__ void mlp_kernel(const float* __restrict__ W1, const float* __restrict__ b1,
                           const float* __restrict__ W2, const float* __restrict__ b2) {
    __shared__ float hid[HID];
    __shared__ float params[32];
    int p = blockIdx.x;
    int i = p / W_, j = p % W_;
    float ri = (float)i / 47.0f;
    float cj = (float)j / 47.0f;
    int t = threadIdx.x;   // 128 threads
#pragma unroll
    for (int q = 0; q < 4; q++) {
        int n = t + 128 * q;
        float v = W1[2 * n] * ri + W1[2 * n + 1] * cj + b1[n];
        hid[n] = fmaxf(v, 0.0f);
    }
    __syncthreads();
    if (t < 27) {
        float s0 = b2[t], s1 = 0.f, s2 = 0.f, s3 = 0.f;
        const float* w2r = W2 + (size_t)t * HID;
        for (int n = 0; n < HID; n += 4) {
            s0 += hid[n] * w2r[n];
            s1 += hid[n + 1] * w2r[n + 1];
            s2 += hid[n + 2] * w2r[n + 2];
            s3 += hid[n + 3] * w2r[n + 3];
        }
        params[t] = (s0 + s1) + (s2 + s3);
    }
    __syncthreads();
    if (t < NK) {
        int k = t;
        float mrh = params[2 * k];
        float mrw = params[2 * k + 1];
        float sr  = params[18 + k];
        float sch = ri * 0.9999f + 5e-5f;
        float scw = cj * 0.9999f + 5e-5f;
        float midh = logf(sch / (1.0f - sch));
        float midw = logf(scw / (1.0f - scw));
        float mh = 47.0f / (1.0f + expf(-(midh + 0.1f * mrh)));
        float mw = 47.0f / (1.0f + expf(-(midw + 0.1f * mrw)));
        float sp = sr + 2.0f;
        float spl = (sp > 20.0f) ? sp : log1pf(expf(sp));
        float sig = (spl + 0.05f) * (48.0f * 0.05f);
        g_pk[p * NK + k] = make_float4(mh, mw, sig, 0.0f);
    }
}

// ---------------- kernel 2: candidate cells, dedup, normalized weights ----------------
__global__ void weights_kernel(const int* __restrict__ gints, const int* __restrict__ roff) {
    int t = blockIdx.x * 256 + threadIdx.x;
    if (t >= NB * NP * NK) return;
    int k = t % NK;
    int p = (t / NK) % NP;
    float4 pk = g_pk[p * NK + k];
    float mh = pk.x, mw = pk.y, sig = pk.z;
    int flh = (int)floorf(mh);
    int flw = (int)floorf(mw);

    int r[8], c[8];
    r[0] = flh;     c[0] = flw;
    r[1] = flh;     c[1] = flw + 1;
    r[2] = flh + 1; c[2] = flw;
    r[3] = flh + 1; c[3] = flw + 1;
    int4 g  = *(const int4*)(gints + (size_t)t * 4);
    r[4] = g.x;  c[4] = g.y;
    r[5] = g.z;  c[5] = g.w;
    int4 ro = *(const int4*)(roff + (size_t)t * 4);
    r[6] = flh + ro.x - 6; c[6] = flw + ro.y - 6;
    r[7] = flh + ro.z - 6; c[7] = flw + ro.w - 6;
#pragma unroll
    for (int v = 0; v < 8; v++) {
        r[v] = (r[v] + 48) % 48;
        c[v] = (c[v] + 48) % 48;
    }

    float inv_s = 1.0f / sig;
    float pr[8];
    float sum = 0.0f;
#pragma unroll
    for (int v = 0; v < 8; v++) {
        bool dup = false;
#pragma unroll
        for (int u = 0; u < 8; u++)
            if (u < v && r[v] == r[u] && c[v] == c[u]) dup = true;
        float dh = ((float)r[v] - mh) * inv_s;
        float dw = ((float)c[v] - mw) * inv_s;
        float e = dup ? 0.0f : expf(-0.5f * (dh * dh + dw * dw));
        pr[v] = e;
        sum += e;
    }
    float inv = 1.0f / sum;
    float wv[8];
    int   lv[8];
#pragma unroll
    for (int v = 0; v < 8; v++) {
        wv[v] = pr[v] * inv;
        lv[v] = r[v] * 48 + c[v];
    }
    *(float4*)(g_wts + (size_t)t * 8)     = make_float4(wv[0], wv[1], wv[2], wv[3]);
    *(float4*)(g_wts + (size_t)t * 8 + 4) = make_float4(wv[4], wv[5], wv[6], wv[7]);
    *(int4*)(g_lin + (size_t)t * 8)       = make_int4(lv[0], lv[1], lv[2], lv[3]);
    *(int4*)(g_lin + (size_t)t * 8 + 4)   = make_int4(lv[4], lv[5], lv[6], lv[7]);
}

// ---------------- kernel 3a: build A (gather + weight + tf32 round) -> global ----------------
// thread = (bp, c4): loops kk. Writes coalesced 512B per warp row-chunk.
__global__ void build_a_kernel() {
    int t = blockIdx.x * 256 + threadIdx.x;      // NB*NP*32 = 589824
    int c4 = t & 31;
    int bp = t >> 5;
    int b  = bp / NP;
    const float* xtb = g_xt + (size_t)b * NP * CIN;
    float* arow = g_af + (size_t)bp * KC;

    for (int kk = 0; kk < NK; kk++) {
        int wb = (bp * NK + kk) * VS8;
        float4 w0 = *(const float4*)(g_wts + wb);
        float4 w1 = *(const float4*)(g_wts + wb + 4);
        int4   l0 = *(const int4*)(g_lin + wb);
        int4   l1 = *(const int4*)(g_lin + wb + 4);
        float4 a = make_float4(0.f, 0.f, 0.f, 0.f);
#define GATH(WV, LV)                                                            \
        {                                                                       \
            float4 rv = *(const float4*)(xtb + (size_t)(LV) * CIN + c4 * 4);    \
            a.x += (WV) * rv.x; a.y += (WV) * rv.y;                             \
            a.z += (WV) * rv.z; a.w += (WV) * rv.w;                             \
        }
        GATH(w0.x, l0.x) GATH(w0.y, l0.y) GATH(w0.z, l0.z) GATH(w0.w, l0.w)
        GATH(w1.x, l1.x) GATH(w1.y, l1.y) GATH(w1.z, l1.z) GATH(w1.w, l1.w)
#undef GATH
        uint4 o;
        o.x = f2tf32(a.x); o.y = f2tf32(a.y); o.z = f2tf32(a.z); o.w = f2tf32(a.w);
        *(uint4*)(arow + kk * KT + c4 * 4) = o;
    }
}

// ---------------- kernel 3b: pipelined tf32 GEMM: out = A @ Wu^T + bu ----------------
// A: g_af [18432][1152], B: g_wub2 [256][1152]. 3-stage cp.async pipeline.
__global__ void __launch_bounds__(256, 2) gemm2_kernel(const float* __restrict__ bu,
                                                       float* __restrict__ out) {
    extern __shared__ char smem[];
    uint32_t sb = smem_u32(smem);
    int tid = threadIdx.x;
    int wid = tid >> 5;
    int lid = tid & 31;

    int m0 = blockIdx.x * GBM;
    int n0 = blockIdx.y * GBN;
    int b  = m0 / NP;
    int p0 = m0 % NP;

    // warp tiling: 2 warps in M (64 each), 4 in N (32 each)
    int wm = wid & 1;
    int wn = wid >> 1;
    int mbase = wm * 64;
    int nbase = wn * 32;

    // tf32-via-b16 ldmatrix lane components
    int a_row  = (lid & 7) + ((lid >> 3) & 1) * 8;
    int a_ksel = (lid >> 4) * 4;
    int b_row  = (lid & 7) + ((lid >> 4) & 1) * 8;
    int b_ksel = ((lid >> 3) & 1) * 4;

    float acc[4][4][4];
#pragma unroll
    for (int i = 0; i < 4; i++)
#pragma unroll
        for (int j = 0; j < 4; j++)
#pragma unroll
            for (int q = 0; q < 4; q++) acc[i][j][q] = 0.0f;

    const float* abase = g_af + (size_t)m0 * KC;
    const float* bbase = g_wub2 + (size_t)n0 * KC;

    // stage copy: 1024 16B chunks A + 1024 B; 4 each per thread
#define ISSUE_STAGE(KT_IDX)                                                       \
    {                                                                             \
        int st = (KT_IDX) % GST;                                                  \
        uint32_t da = sb + st * STAGE_SZ;                                         \
        uint32_t db = da + STAGE_A;                                               \
        const float* sa = abase + (KT_IDX) * GBK;                                 \
        const float* sg = bbase + (KT_IDX) * GBK;                                 \
        _Pragma("unroll")                                                         \
        for (int q = 0; q < 4; q++) {                                             \
            int idx = q * 256 + tid;                                              \
            int row = idx >> 3, c16 = idx & 7;                                    \
            cp_async16(da + row * GRPB + c16 * 16, sa + (size_t)row * KC + c16 * 4); \
            cp_async16(db + row * GRPB + c16 * 16, sg + (size_t)row * KC + c16 * 4); \
        }                                                                         \
        cp_commit();                                                              \
    }

    ISSUE_STAGE(0)
    ISSUE_STAGE(1)

    const int NKT = KC / GBK;    // 36
    for (int kt = 0; kt < NKT; kt++) {
        if (kt + GST - 1 < NKT) {
            asm volatile("cp.async.wait_group %0;" :: "n"(GST - 2));
        } else {
            asm volatile("cp.async.wait_group 0;" ::: "memory");
        }
        __syncthreads();
        if (kt + GST - 1 < NKT) ISSUE_STAGE(kt + GST - 1)

        uint32_t base = sb + (kt % GST) * STAGE_SZ;
#pragma unroll
        for (int ks = 0; ks < 4; ks++) {
            int kc = ks * 8;
            uint32_t bf[8];
            uint32_t addr0 = base + STAGE_A + (nbase + b_row) * GRPB + (kc + b_ksel) * 4;
            uint32_t addr1 = base + STAGE_A + (nbase + 16 + b_row) * GRPB + (kc + b_ksel) * 4;
            ldm_x4(bf, addr0);
            ldm_x4(bf + 4, addr1);
#pragma unroll
            for (int mf = 0; mf < 4; mf++) {
                uint32_t af[4];
                uint32_t aaddr = base + (mbase + mf * 16 + a_row) * GRPB + (kc + a_ksel) * 4;
                ldm_x4(af, aaddr);
#pragma unroll
                for (int nf = 0; nf < 4; nf++)
                    mma_tf32(acc[mf][nf], af, bf + nf * 2);
            }
        }
        __syncthreads();
    }
#undef ISSUE_STAGE

    // ---- epilogue: + bias, store to out[b][co][p] ----
    int grp = lid >> 2;
    int tg  = lid & 3;
    size_t ob = (size_t)b * COUT * NP + p0 + mbase;
#pragma unroll
    for (int nf = 0; nf < 4; nf++) {
        int col0 = n0 + nbase + nf * 8 + tg * 2;
        float bb0 = bu[col0];
        float bb1 = bu[col0 + 1];
        size_t o0 = ob + (size_t)col0 * NP;
        size_t o1 = ob + (size_t)(col0 + 1) * NP;
#pragma unroll
        for (int mf = 0; mf < 4; mf++) {
            int rr = mf * 16 + grp;
            out[o0 + rr]     = acc[mf][nf][0] + bb0;
            out[o1 + rr]     = acc[mf][nf][1] + bb1;
            out[o0 + rr + 8] = acc[mf][nf][2] + bb0;
            out[o1 + rr + 8] = acc[mf][nf][3] + bb1;
        }
    }
}

// ---------------- launch ----------------
extern "C" void kernel_launch(void* const* d_in, const int* in_sizes, int n_in,
                              void* d_out, int out_size) {
    const float* x     = (const float*)d_in[0];
    const float* W1    = (const float*)d_in[1];
    const float* b1    = (const float*)d_in[2];
    const float* W2    = (const float*)d_in[3];
    const float* b2    = (const float*)d_in[4];
    const float* Wu    = (const float*)d_in[5];
    const float* bu    = (const float*)d_in[6];
    const int*   gints = (const int*)d_in[7];
    const int*   roff  = (const int*)d_in[8];
    float* out = (float*)d_out;

    {
        dim3 blk(32, 8);
        dim3 grd(NP / 32, CIN / 32, NB);
        transpose_x_kernel<<<grd, blk>>>(x);
    }
    wu_prep_kernel<<<(COUT * KC / 4 + 255) / 256, 256>>>(Wu);
    mlp_kernel<<<NP, 128>>>(W1, b1, W2, b2);
    {
        int items = NB * NP * NK;
        weights_kernel<<<(items + 255) / 256, 256>>>(gints, roff);
    }
    build_a_kernel<<<(NB * NP * 32) / 256, 256>>>();
    cudaFuncSetAttribute(gemm2_kernel, cudaFuncAttributeMaxDynamicSharedMemorySize, SM_TOTAL);
    {
        dim3 grd(NB * NP / GBM, COUT / GBN);
        gemm2_kernel<<<grd, 256, SM_TOTAL>>>(bu, out);
    }
}

// round 10
// speedup vs baseline: 1.2227x; 1.2227x over previous
#include <cuda_runtime.h>
#include <cuda_fp16.h>
#include <math.h>
#include <stdint.h>

#define H_   48
#define W_   48
#define NP   2304        // H_*W_
#define NB   8
#define CIN  128
#define COUT 256
#define NK   9
#define HID  512
#define KC   1152        // NK*CIN
#define VS8  8

// GEMM tiling (fp16, m16n8k16)
#define GBM 128
#define GBN 128
#define GBK 64
#define GST 3            // pipeline stages
#define GRPB 144         // bytes per smem row: 64 fp16 = 128B + 16B pad (mod128==16 -> conflict-free)
#define STAGE_A (GBM * GRPB)             // 18432
#define STAGE_B (GBN * GRPB)             // 18432
#define STAGE_SZ (STAGE_A + STAGE_B)     // 36864
#define SM_TOTAL (GST * STAGE_SZ)        // 110592

// ---------------- scratch (static device globals; no allocation) ----------------
__device__ __half g_xt [NB * NP * CIN];        // x transposed to [b][p][c], fp16 (4.7MB)
__device__ float4 g_pk [NP * NK];              // mean_h, mean_w, sigma
__device__ float  g_wts[NB * NP * NK * VS8];
__device__ int    g_lin[NB * NP * NK * VS8];
__device__ __half g_wuh[COUT * KC];            // Wu fp16, [n][k] contiguous (0.6MB)
__device__ __half g_af [NB * NP * KC];         // gathered A, fp16 (42.5MB)

// ---------------- helpers ----------------
__device__ __forceinline__ uint32_t smem_u32(const void* p) {
    uint32_t a;
    asm("{ .reg .u64 t; cvta.to.shared.u64 t, %1; cvt.u32.u64 %0, t; }" : "=r"(a) : "l"(p));
    return a;
}
__device__ __forceinline__ void ldm_x4(uint32_t* r, uint32_t addr) {
    asm volatile("ldmatrix.sync.aligned.m8n8.x4.shared.b16 {%0,%1,%2,%3}, [%4];"
                 : "=r"(r[0]), "=r"(r[1]), "=r"(r[2]), "=r"(r[3]) : "r"(addr));
}
__device__ __forceinline__ void mma_f16(float* d, const uint32_t* a, const uint32_t* b) {
    asm volatile("mma.sync.aligned.m16n8k16.row.col.f32.f16.f16.f32 "
                 "{%0,%1,%2,%3}, {%4,%5,%6,%7}, {%8,%9}, {%0,%1,%2,%3};"
                 : "+f"(d[0]), "+f"(d[1]), "+f"(d[2]), "+f"(d[3])
                 : "r"(a[0]), "r"(a[1]), "r"(a[2]), "r"(a[3]), "r"(b[0]), "r"(b[1]));
}
__device__ __forceinline__ void cp_async16(uint32_t dst, const void* src) {
    asm volatile("cp.async.cg.shared.global [%0], [%1], 16;" :: "r"(dst), "l"(src) : "memory");
}
__device__ __forceinline__ void cp_commit() {
    asm volatile("cp.async.commit_group;" ::: "memory");
}

// ---------------- kernel 0a: transpose x (b,c,p) -> (b,p,c), fp32 -> fp16 ----------------
__global__ void transpose_x_kernel(const float* __restrict__ in) {
    __shared__ float tile[32][33];
    int b = blockIdx.z;
    const float* inb = in + (size_t)b * CIN * NP;
    __half* outb = g_xt + (size_t)b * NP * CIN;
    int c0 = blockIdx.x * 32;
    int r0 = blockIdx.y * 32;
    int tx = threadIdx.x, ty = threadIdx.y;
#pragma unroll
    for (int q = 0; q < 32; q += 8)
        tile[ty + q][tx] = inb[(r0 + ty + q) * NP + c0 + tx];
    __syncthreads();
#pragma unroll
    for (int q = 0; q < 32; q += 8)
        outb[(size_t)(c0 + ty + q) * CIN + r0 + tx] = __float2half_rn(tile[tx][ty + q]);
}

// ---------------- kernel 0b: Wu fp32 -> fp16 contiguous ----------------
__global__ void wu_prep_kernel(const float* __restrict__ wu) {
    int t = blockIdx.x * 256 + threadIdx.x;      // COUT*KC/8 = 36864
    if (t >= COUT * KC / 8) return;
    float4 v0 = ((const float4*)wu)[t * 2];
    float4 v1 = ((const float4*)wu)[t * 2 + 1];
    __half2 h[4];
    h[0] = __floats2half2_rn(v0.x, v0.y);
    h[1] = __floats2half2_rn(v0.z, v0.w);
    h[2] = __floats2half2_rn(v1.x, v1.y);
    h[3] = __floats2half2_rn(v1.z, v1.w);
    ((uint4*)g_wuh)[t] = *(uint4*)h;
}

// ---------------- kernel 1: per-pixel MLP -> means / sigma ----------------
__global__ void mlp_kernel(const float* __restrict__ W1, const float* __restrict__ b1,
                           const float* __restrict__ W2, const float* __restrict__ b2) {
    __shared__ float hid[HID];
    __shared__ float params[32];
    int p = blockIdx.x;
    int i = p / W_, j = p % W_;
    float ri = (float)i / 47.0f;
    float cj = (float)j / 47.0f;
    int t = threadIdx.x;   // 128 threads
#pragma unroll
    for (int q = 0; q < 4; q++) {
        int n = t + 128 * q;
        float v = W1[2 * n] * ri + W1[2 * n + 1] * cj + b1[n];
        hid[n] = fmaxf(v, 0.0f);
    }
    __syncthreads();
    if (t < 27) {
        float s0 = b2[t], s1 = 0.f, s2 = 0.f, s3 = 0.f;
        const float* w2r = W2 + (size_t)t * HID;
        for (int n = 0; n < HID; n += 4) {
            s0 += hid[n] * w2r[n];
            s1 += hid[n + 1] * w2r[n + 1];
            s2 += hid[n + 2] * w2r[n + 2];
            s3 += hid[n + 3] * w2r[n + 3];
        }
        params[t] = (s0 + s1) + (s2 + s3);
    }
    __syncthreads();
    if (t < NK) {
        int k = t;
        float mrh = params[2 * k];
        float mrw = params[2 * k + 1];
        float sr  = params[18 + k];
        float sch = ri * 0.9999f + 5e-5f;
        float scw = cj * 0.9999f + 5e-5f;
        float midh = logf(sch / (1.0f - sch));
        float midw = logf(scw / (1.0f - scw));
        float mh = 47.0f / (1.0f + expf(-(midh + 0.1f * mrh)));
        float mw = 47.0f / (1.0f + expf(-(midw + 0.1f * mrw)));
        float sp = sr + 2.0f;
        float spl = (sp > 20.0f) ? sp : log1pf(expf(sp));
        float sig = (spl + 0.05f) * (48.0f * 0.05f);
        g_pk[p * NK + k] = make_float4(mh, mw, sig, 0.0f);
    }
}

// ---------------- kernel 2: candidate cells, dedup, normalized weights ----------------
__global__ void weights_kernel(const int* __restrict__ gints, const int* __restrict__ roff) {
    int t = blockIdx.x * 256 + threadIdx.x;
    if (t >= NB * NP * NK) return;
    int k = t % NK;
    int p = (t / NK) % NP;
    float4 pk = g_pk[p * NK + k];
    float mh = pk.x, mw = pk.y, sig = pk.z;
    int flh = (int)floorf(mh);
    int flw = (int)floorf(mw);

    int r[8], c[8];
    r[0] = flh;     c[0] = flw;
    r[1] = flh;     c[1] = flw + 1;
    r[2] = flh + 1; c[2] = flw;
    r[3] = flh + 1; c[3] = flw + 1;
    int4 g  = *(const int4*)(gints + (size_t)t * 4);
    r[4] = g.x;  c[4] = g.y;
    r[5] = g.z;  c[5] = g.w;
    int4 ro = *(const int4*)(roff + (size_t)t * 4);
    r[6] = flh + ro.x - 6; c[6] = flw + ro.y - 6;
    r[7] = flh + ro.z - 6; c[7] = flw + ro.w - 6;
#pragma unroll
    for (int v = 0; v < 8; v++) {
        r[v] = (r[v] + 48) % 48;
        c[v] = (c[v] + 48) % 48;
    }

    float inv_s = 1.0f / sig;
    float pr[8];
    float sum = 0.0f;
#pragma unroll
    for (int v = 0; v < 8; v++) {
        bool dup = false;
#pragma unroll
        for (int u = 0; u < 8; u++)
            if (u < v && r[v] == r[u] && c[v] == c[u]) dup = true;
        float dh = ((float)r[v] - mh) * inv_s;
        float dw = ((float)c[v] - mw) * inv_s;
        float e = dup ? 0.0f : expf(-0.5f * (dh * dh + dw * dw));
        pr[v] = e;
        sum += e;
    }
    float inv = 1.0f / sum;
    float wv[8];
    int   lv[8];
#pragma unroll
    for (int v = 0; v < 8; v++) {
        wv[v] = pr[v] * inv;
        lv[v] = r[v] * 48 + c[v];
    }
    *(float4*)(g_wts + (size_t)t * 8)     = make_float4(wv[0], wv[1], wv[2], wv[3]);
    *(float4*)(g_wts + (size_t)t * 8 + 4) = make_float4(wv[4], wv[5], wv[6], wv[7]);
    *(int4*)(g_lin + (size_t)t * 8)       = make_int4(lv[0], lv[1], lv[2], lv[3]);
    *(int4*)(g_lin + (size_t)t * 8 + 4)   = make_int4(lv[4], lv[5], lv[6], lv[7]);
}

// ---------------- kernel 3a: build A (fp16 gather + fp32 weight + fp16 store) ----------------
// thread = (bp, c8): 8 channels (16B) per thread, loops kk.
__global__ void build_a_kernel() {
    int t = blockIdx.x * 256 + threadIdx.x;      // NB*NP*16 = 294912
    int c8 = t & 15;
    int bp = t >> 4;
    int b  = bp / NP;
    const __half* xtb = g_xt + (size_t)b * NP * CIN;
    __half* arow = g_af + (size_t)bp * KC;

    for (int kk = 0; kk < NK; kk++) {
        int wb = (bp * NK + kk) * VS8;
        float4 w0 = *(const float4*)(g_wts + wb);
        float4 w1 = *(const float4*)(g_wts + wb + 4);
        int4   l0 = *(const int4*)(g_lin + wb);
        int4   l1 = *(const int4*)(g_lin + wb + 4);
        float a[8];
#pragma unroll
        for (int q = 0; q < 8; q++) a[q] = 0.0f;
#define GATH(WV, LV)                                                              \
        {                                                                         \
            uint4 rv = *(const uint4*)(xtb + (size_t)(LV) * CIN + c8 * 8);        \
            const __half2* h2 = (const __half2*)&rv;                              \
            _Pragma("unroll")                                                     \
            for (int q = 0; q < 4; q++) {                                         \
                float2 f = __half22float2(h2[q]);                                 \
                a[q * 2]     += (WV) * f.x;                                       \
                a[q * 2 + 1] += (WV) * f.y;                                       \
            }                                                                     \
        }
        GATH(w0.x, l0.x) GATH(w0.y, l0.y) GATH(w0.z, l0.z) GATH(w0.w, l0.w)
        GATH(w1.x, l1.x) GATH(w1.y, l1.y) GATH(w1.z, l1.z) GATH(w1.w, l1.w)
#undef GATH
        __half2 o[4];
#pragma unroll
        for (int q = 0; q < 4; q++)
            o[q] = __floats2half2_rn(a[q * 2], a[q * 2 + 1]);
        *(uint4*)(arow + kk * CIN + c8 * 8) = *(uint4*)o;
    }
}

// ---------------- kernel 3b: pipelined fp16 GEMM: out = A @ Wu^T + bu ----------------
__global__ void __launch_bounds__(256, 2) gemm2_kernel(const float* __restrict__ bu,
                                                       float* __restrict__ out) {
    extern __shared__ char smem[];
    uint32_t sb = smem_u32(smem);
    int tid = threadIdx.x;
    int wid = tid >> 5;
    int lid = tid & 31;

    int m0 = blockIdx.x * GBM;
    int n0 = blockIdx.y * GBN;
    int b  = m0 / NP;
    int p0 = m0 % NP;

    // warp tiling: 2 warps in M (64 each), 4 in N (32 each)
    int wm = wid & 1;
    int wn = wid >> 1;
    int mbase = wm * 64;
    int nbase = wn * 32;

    // fp16 ldmatrix lane components (verified in round 7)
    int a_row = (lid & 15);
    int a_col = (lid >> 4) * 8;
    int b_row = (lid & 7) + ((lid >> 4) & 1) * 8;
    int b_col = ((lid >> 3) & 1) * 8;

    float acc[4][4][4];
#pragma unroll
    for (int i = 0; i < 4; i++)
#pragma unroll
        for (int j = 0; j < 4; j++)
#pragma unroll
            for (int q = 0; q < 4; q++) acc[i][j][q] = 0.0f;

    const __half* abase = g_af + (size_t)m0 * KC;
    const __half* bbase = g_wuh + (size_t)n0 * KC;

    // stage copy: 128 rows x 8 chunks (16B) for A and B; 4 each per thread
#define ISSUE_STAGE(KT_IDX)                                                         \
    {                                                                               \
        int st = (KT_IDX) % GST;                                                    \
        uint32_t da = sb + st * STAGE_SZ;                                           \
        uint32_t db = da + STAGE_A;                                                 \
        const __half* sa = abase + (KT_IDX) * GBK;                                  \
        const __half* sg = bbase + (KT_IDX) * GBK;                                  \
        _Pragma("unroll")                                                           \
        for (int q = 0; q < 4; q++) {                                               \
            int idx = q * 256 + tid;                                                \
            int row = idx >> 3, c16 = idx & 7;                                      \
            cp_async16(da + row * GRPB + c16 * 16, sa + (size_t)row * KC + c16 * 8);\
            cp_async16(db + row * GRPB + c16 * 16, sg + (size_t)row * KC + c16 * 8);\
        }                                                                           \
        cp_commit();                                                                \
    }

    ISSUE_STAGE(0)
    ISSUE_STAGE(1)

    const int NKT = KC / GBK;    // 18
    for (int kt = 0; kt < NKT; kt++) {
        if (kt + GST - 1 < NKT) {
            asm volatile("cp.async.wait_group %0;" :: "n"(GST - 2));
        } else {
            asm volatile("cp.async.wait_group 0;" ::: "memory");
        }
        __syncthreads();
        if (kt + GST - 1 < NKT) ISSUE_STAGE(kt + GST - 1)

        uint32_t base = sb + (kt % GST) * STAGE_SZ;
#pragma unroll
        for (int ks = 0; ks < 4; ks++) {
            int kc = ks * 16;
            uint32_t bf[8];
            uint32_t addr0 = base + STAGE_A + (nbase + b_row) * GRPB + (kc + b_col) * 2;
            uint32_t addr1 = base + STAGE_A + (nbase + 16 + b_row) * GRPB + (kc + b_col) * 2;
            ldm_x4(bf, addr0);
            ldm_x4(bf + 4, addr1);
#pragma unroll
            for (int mf = 0; mf < 4; mf++) {
                uint32_t af[4];
                uint32_t aaddr = base + (mbase + mf * 16 + a_row) * GRPB + (kc + a_col) * 2;
                ldm_x4(af, aaddr);
#pragma unroll
                for (int nf = 0; nf < 4; nf++)
                    mma_f16(acc[mf][nf], af, bf + nf * 2);
            }
        }
        __syncthreads();
    }
#undef ISSUE_STAGE

    // ---- epilogue: + bias, store to out[b][co][p] ----
    int grp = lid >> 2;
    int tg  = lid & 3;
    size_t ob = (size_t)b * COUT * NP + p0 + mbase;
#pragma unroll
    for (int nf = 0; nf < 4; nf++) {
        int col0 = n0 + nbase + nf * 8 + tg * 2;
        float bb0 = bu[col0];
        float bb1 = bu[col0 + 1];
        size_t o0 = ob + (size_t)col0 * NP;
        size_t o1 = ob + (size_t)(col0 + 1) * NP;
#pragma unroll
        for (int mf = 0; mf < 4; mf++) {
            int rr = mf * 16 + grp;
            out[o0 + rr]     = acc[mf][nf][0] + bb0;
            out[o1 + rr]     = acc[mf][nf][1] + bb1;
            out[o0 + rr + 8] = acc[mf][nf][2] + bb0;
            out[o1 + rr + 8] = acc[mf][nf][3] + bb1;
        }
    }
}

// ---------------- launch ----------------
extern "C" void kernel_launch(void* const* d_in, const int* in_sizes, int n_in,
                              void* d_out, int out_size) {
    const float* x     = (const float*)d_in[0];
    const float* W1    = (const float*)d_in[1];
    const float* b1    = (const float*)d_in[2];
    const float* W2    = (const float*)d_in[3];
    const float* b2    = (const float*)d_in[4];
    const float* Wu    = (const float*)d_in[5];
    const float* bu    = (const float*)d_in[6];
    const int*   gints = (const int*)d_in[7];
    const int*   roff  = (const int*)d_in[8];
    float* out = (float*)d_out;

    {
        dim3 blk(32, 8);
        dim3 grd(NP / 32, CIN / 32, NB);
        transpose_x_kernel<<<grd, blk>>>(x);
    }
    wu_prep_kernel<<<(COUT * KC / 8 + 255) / 256, 256>>>(Wu);
    mlp_kernel<<<NP, 128>>>(W1, b1, W2, b2);
    {
        int items = NB * NP * NK;
        weights_kernel<<<(items + 255) / 256, 256>>>(gints, roff);
    }
    build_a_kernel<<<(NB * NP * 16) / 256, 256>>>();
    cudaFuncSetAttribute(gemm2_kernel, cudaFuncAttributeMaxDynamicSharedMemorySize, SM_TOTAL);
    {
        dim3 grd(NB * NP / GBM, COUT / GBN);
        gemm2_kernel<<<grd, 256, SM_TOTAL>>>(bu, out);
    }
}

// round 11
// speedup vs baseline: 1.6128x; 1.3191x over previous
#include <cuda_runtime.h>
#include <cuda_fp16.h>
#include <math.h>
#include <stdint.h>

#define H_   48
#define W_   48
#define NP   2304        // H_*W_
#define NB   8
#define CIN  128
#define COUT 256
#define NK   9
#define HID  512
#define KC   1152        // NK*CIN
#define VS8  8

// GEMM tiling (fp16, m16n8k16)
#define GBM 128
#define GBN 128
#define GBK 64
#define GST 3            // pipeline stages
#define GRPB 144         // bytes per smem row: 64 fp16 = 128B + 16B pad (mod128==16 -> conflict-free)
#define STAGE_A (GBM * GRPB)             // 18432
#define STAGE_B (GBN * GRPB)             // 18432
#define STAGE_SZ (STAGE_A + STAGE_B)     // 36864
#define SM_TOTAL (GST * STAGE_SZ)        // 110592

// ---------------- scratch (static device globals; no allocation) ----------------
__device__ __half g_xt [NB * NP * CIN];        // x transposed to [b][p][c], fp16 (4.7MB)
__device__ float4 g_pk [NP * NK];              // mean_h, mean_w, sigma
__device__ float  g_wts[NB * NP * NK * VS8];
__device__ int    g_lin[NB * NP * NK * VS8];
__device__ __half g_wuh[COUT * KC];            // Wu fp16, [n][k] contiguous (0.6MB)
__device__ __half g_af [NB * NP * KC];         // gathered A, fp16 (42.5MB)
__device__ float  g_w2t[HID * 32];             // W2 transposed [n][o], zero-padded to 32

// ---------------- helpers ----------------
__device__ __forceinline__ uint32_t smem_u32(const void* p) {
    uint32_t a;
    asm("{ .reg .u64 t; cvta.to.shared.u64 t, %1; cvt.u32.u64 %0, t; }" : "=r"(a) : "l"(p));
    return a;
}
__device__ __forceinline__ void ldm_x4(uint32_t* r, uint32_t addr) {
    asm volatile("ldmatrix.sync.aligned.m8n8.x4.shared.b16 {%0,%1,%2,%3}, [%4];"
                 : "=r"(r[0]), "=r"(r[1]), "=r"(r[2]), "=r"(r[3]) : "r"(addr));
}
__device__ __forceinline__ void mma_f16(float* d, const uint32_t* a, const uint32_t* b) {
    asm volatile("mma.sync.aligned.m16n8k16.row.col.f32.f16.f16.f32 "
                 "{%0,%1,%2,%3}, {%4,%5,%6,%7}, {%8,%9}, {%0,%1,%2,%3};"
                 : "+f"(d[0]), "+f"(d[1]), "+f"(d[2]), "+f"(d[3])
                 : "r"(a[0]), "r"(a[1]), "r"(a[2]), "r"(a[3]), "r"(b[0]), "r"(b[1]));
}
__device__ __forceinline__ void cp_async16(uint32_t dst, const void* src) {
    asm volatile("cp.async.cg.shared.global [%0], [%1], 16;" :: "r"(dst), "l"(src) : "memory");
}
__device__ __forceinline__ void cp_commit() {
    asm volatile("cp.async.commit_group;" ::: "memory");
}

// ---------------- kernel 0a: transpose x (b,c,p) -> (b,p,c), fp32 -> fp16 ----------------
__global__ void transpose_x_kernel(const float* __restrict__ in) {
    __shared__ float tile[32][33];
    int b = blockIdx.z;
    const float* inb = in + (size_t)b * CIN * NP;
    __half* outb = g_xt + (size_t)b * NP * CIN;
    int c0 = blockIdx.x * 32;
    int r0 = blockIdx.y * 32;
    int tx = threadIdx.x, ty = threadIdx.y;
#pragma unroll
    for (int q = 0; q < 32; q += 8)
        tile[ty + q][tx] = inb[(r0 + ty + q) * NP + c0 + tx];
    __syncthreads();
#pragma unroll
    for (int q = 0; q < 32; q += 8)
        outb[(size_t)(c0 + ty + q) * CIN + r0 + tx] = __float2half_rn(tile[tx][ty + q]);
}

// ---------------- kernel 0b: Wu fp32 -> fp16 contiguous ----------------
__global__ void wu_prep_kernel(const float* __restrict__ wu) {
    int t = blockIdx.x * 256 + threadIdx.x;      // COUT*KC/8 = 36864
    if (t >= COUT * KC / 8) return;
    float4 v0 = ((const float4*)wu)[t * 2];
    float4 v1 = ((const float4*)wu)[t * 2 + 1];
    __half2 h[4];
    h[0] = __floats2half2_rn(v0.x, v0.y);
    h[1] = __floats2half2_rn(v0.z, v0.w);
    h[2] = __floats2half2_rn(v1.x, v1.y);
    h[3] = __floats2half2_rn(v1.z, v1.w);
    ((uint4*)g_wuh)[t] = *(uint4*)h;
}

// ---------------- kernel 0c: W2 [27][512] -> W2T [512][32] (zero padded) ----------------
__global__ void w2t_prep_kernel(const float* __restrict__ W2) {
    int t = blockIdx.x * 256 + threadIdx.x;      // 27*512 = 13824
    if (t >= 27 * HID) return;
    int o = t / HID;
    int n = t % HID;
    g_w2t[n * 32 + o] = W2[t];
}

// ---------------- kernel 1: per-pixel MLP -> means / sigma (coalesced W2T) ----------------
// block = 8 pixels x 32 lanes. Lane o computes param o (o<27) for its pixel:
// recompute hid[n] per-lane (register-only), read W2T coalesced.
__global__ void __launch_bounds__(256) mlp_kernel(const float* __restrict__ W1,
                                                  const float* __restrict__ b1,
                                                  const float* __restrict__ b2) {
    int tid = threadIdx.x;
    int o  = tid & 31;
    int p  = blockIdx.x * 8 + (tid >> 5);
    int i = p / W_, j = p % W_;
    float ri = (float)i / 47.0f;
    float cj = (float)j / 47.0f;

    float s = (o < 27) ? b2[o] : 0.0f;
    const float2* w1f2 = (const float2*)W1;
#pragma unroll 4
    for (int n = 0; n < HID; n++) {
        float2 w1v = __ldg(&w1f2[n]);           // broadcast across warp
        float h = fmaxf(w1v.x * ri + w1v.y * cj + __ldg(&b1[n]), 0.0f);
        s += h * g_w2t[n * 32 + o];             // lanes 0..26 contiguous
    }

    // distribute params via shuffle; lane k (k<9) computes g_pk[p*9+k]
    float mrh = __shfl_sync(0xFFFFFFFFu, s, (o < 9) ? 2 * o : 0);
    float mrw = __shfl_sync(0xFFFFFFFFu, s, (o < 9) ? 2 * o + 1 : 0);
    float sr  = __shfl_sync(0xFFFFFFFFu, s, (o < 9) ? 18 + o : 0);
    if (o < NK) {
        float sch = ri * 0.9999f + 5e-5f;
        float scw = cj * 0.9999f + 5e-5f;
        float midh = logf(sch / (1.0f - sch));
        float midw = logf(scw / (1.0f - scw));
        float mh = 47.0f / (1.0f + expf(-(midh + 0.1f * mrh)));
        float mw = 47.0f / (1.0f + expf(-(midw + 0.1f * mrw)));
        float sp = sr + 2.0f;
        float spl = (sp > 20.0f) ? sp : log1pf(expf(sp));
        float sig = (spl + 0.05f) * (48.0f * 0.05f);
        g_pk[p * NK + o] = make_float4(mh, mw, sig, 0.0f);
    }
}

// ---------------- kernel 2: candidate cells, dedup, normalized weights ----------------
__global__ void weights_kernel(const int* __restrict__ gints, const int* __restrict__ roff) {
    int t = blockIdx.x * 256 + threadIdx.x;
    if (t >= NB * NP * NK) return;
    int k = t % NK;
    int p = (t / NK) % NP;
    float4 pk = g_pk[p * NK + k];
    float mh = pk.x, mw = pk.y, sig = pk.z;
    int flh = (int)floorf(mh);
    int flw = (int)floorf(mw);

    int r[8], c[8];
    r[0] = flh;     c[0] = flw;
    r[1] = flh;     c[1] = flw + 1;
    r[2] = flh + 1; c[2] = flw;
    r[3] = flh + 1; c[3] = flw + 1;
    int4 g  = *(const int4*)(gints + (size_t)t * 4);
    r[4] = g.x;  c[4] = g.y;
    r[5] = g.z;  c[5] = g.w;
    int4 ro = *(const int4*)(roff + (size_t)t * 4);
    r[6] = flh + ro.x - 6; c[6] = flw + ro.y - 6;
    r[7] = flh + ro.z - 6; c[7] = flw + ro.w - 6;
#pragma unroll
    for (int v = 0; v < 8; v++) {
        r[v] = (r[v] + 48) % 48;
        c[v] = (c[v] + 48) % 48;
    }

    float inv_s = 1.0f / sig;
    float pr[8];
    float sum = 0.0f;
#pragma unroll
    for (int v = 0; v < 8; v++) {
        bool dup = false;
#pragma unroll
        for (int u = 0; u < 8; u++)
            if (u < v && r[v] == r[u] && c[v] == c[u]) dup = true;
        float dh = ((float)r[v] - mh) * inv_s;
        float dw = ((float)c[v] - mw) * inv_s;
        float e = dup ? 0.0f : expf(-0.5f * (dh * dh + dw * dw));
        pr[v] = e;
        sum += e;
    }
    float inv = 1.0f / sum;
    float wv[8];
    int   lv[8];
#pragma unroll
    for (int v = 0; v < 8; v++) {
        wv[v] = pr[v] * inv;
        lv[v] = r[v] * 48 + c[v];
    }
    *(float4*)(g_wts + (size_t)t * 8)     = make_float4(wv[0], wv[1], wv[2], wv[3]);
    *(float4*)(g_wts + (size_t)t * 8 + 4) = make_float4(wv[4], wv[5], wv[6], wv[7]);
    *(int4*)(g_lin + (size_t)t * 8)       = make_int4(lv[0], lv[1], lv[2], lv[3]);
    *(int4*)(g_lin + (size_t)t * 8 + 4)   = make_int4(lv[4], lv[5], lv[6], lv[7]);
}

// ---------------- kernel 3a: build A (fp16 gather + fp32 weight + fp16 store) ----------------
__global__ void build_a_kernel() {
    int t = blockIdx.x * 256 + threadIdx.x;      // NB*NP*16 = 294912
    int c8 = t & 15;
    int bp = t >> 4;
    int b  = bp / NP;
    const __half* xtb = g_xt + (size_t)b * NP * CIN;
    __half* arow = g_af + (size_t)bp * KC;

    for (int kk = 0; kk < NK; kk++) {
        int wb = (bp * NK + kk) * VS8;
        float4 w0 = *(const float4*)(g_wts + wb);
        float4 w1 = *(const float4*)(g_wts + wb + 4);
        int4   l0 = *(const int4*)(g_lin + wb);
        int4   l1 = *(const int4*)(g_lin + wb + 4);
        float a[8];
#pragma unroll
        for (int q = 0; q < 8; q++) a[q] = 0.0f;
#define GATH(WV, LV)                                                              \
        {                                                                         \
            uint4 rv = *(const uint4*)(xtb + (size_t)(LV) * CIN + c8 * 8);        \
            const __half2* h2 = (const __half2*)&rv;                              \
            _Pragma("unroll")                                                     \
            for (int q = 0; q < 4; q++) {                                         \
                float2 f = __half22float2(h2[q]);                                 \
                a[q * 2]     += (WV) * f.x;                                       \
                a[q * 2 + 1] += (WV) * f.y;                                       \
            }                                                                     \
        }
        GATH(w0.x, l0.x) GATH(w0.y, l0.y) GATH(w0.z, l0.z) GATH(w0.w, l0.w)
        GATH(w1.x, l1.x) GATH(w1.y, l1.y) GATH(w1.z, l1.z) GATH(w1.w, l1.w)
#undef GATH
        __half2 o[4];
#pragma unroll
        for (int q = 0; q < 4; q++)
            o[q] = __floats2half2_rn(a[q * 2], a[q * 2 + 1]);
        *(uint4*)(arow + kk * CIN + c8 * 8) = *(uint4*)o;
    }
}

// ---------------- kernel 3b: pipelined fp16 GEMM: out = A @ Wu^T + bu ----------------
__global__ void __launch_bounds__(256, 2) gemm2_kernel(const float* __restrict__ bu,
                                                       float* __restrict__ out) {
    extern __shared__ char smem[];
    uint32_t sb = smem_u32(smem);
    int tid = threadIdx.x;
    int wid = tid >> 5;
    int lid = tid & 31;

    int m0 = blockIdx.x * GBM;
    int n0 = blockIdx.y * GBN;
    int b  = m0 / NP;
    int p0 = m0 % NP;

    int wm = wid & 1;
    int wn = wid >> 1;
    int mbase = wm * 64;
    int nbase = wn * 32;

    int a_row = (lid & 15);
    int a_col = (lid >> 4) * 8;
    int b_row = (lid & 7) + ((lid >> 4) & 1) * 8;
    int b_col = ((lid >> 3) & 1) * 8;

    float acc[4][4][4];
#pragma unroll
    for (int i = 0; i < 4; i++)
#pragma unroll
        for (int j = 0; j < 4; j++)
#pragma unroll
            for (int q = 0; q < 4; q++) acc[i][j][q] = 0.0f;

    const __half* abase = g_af + (size_t)m0 * KC;
    const __half* bbase = g_wuh + (size_t)n0 * KC;

#define ISSUE_STAGE(KT_IDX)                                                         \
    {                                                                               \
        int st = (KT_IDX) % GST;                                                    \
        uint32_t da = sb + st * STAGE_SZ;                                           \
        uint32_t db = da + STAGE_A;                                                 \
        const __half* sa = abase + (KT_IDX) * GBK;                                  \
        const __half* sg = bbase + (KT_IDX) * GBK;                                  \
        _Pragma("unroll")                                                           \
        for (int q = 0; q < 4; q++) {                                               \
            int idx = q * 256 + tid;                                                \
            int row = idx >> 3, c16 = idx & 7;                                      \
            cp_async16(da + row * GRPB + c16 * 16, sa + (size_t)row * KC + c16 * 8);\
            cp_async16(db + row * GRPB + c16 * 16, sg + (size_t)row * KC + c16 * 8);\
        }                                                                           \
        cp_commit();                                                                \
    }

    ISSUE_STAGE(0)
    ISSUE_STAGE(1)

    const int NKT = KC / GBK;    // 18
    for (int kt = 0; kt < NKT; kt++) {
        if (kt + GST - 1 < NKT) {
            asm volatile("cp.async.wait_group %0;" :: "n"(GST - 2));
        } else {
            asm volatile("cp.async.wait_group 0;" ::: "memory");
        }
        __syncthreads();
        if (kt + GST - 1 < NKT) ISSUE_STAGE(kt + GST - 1)

        uint32_t base = sb + (kt % GST) * STAGE_SZ;
#pragma unroll
        for (int ks = 0; ks < 4; ks++) {
            int kc = ks * 16;
            uint32_t bf[8];
            uint32_t addr0 = base + STAGE_A + (nbase + b_row) * GRPB + (kc + b_col) * 2;
            uint32_t addr1 = base + STAGE_A + (nbase + 16 + b_row) * GRPB + (kc + b_col) * 2;
            ldm_x4(bf, addr0);
            ldm_x4(bf + 4, addr1);
#pragma unroll
            for (int mf = 0; mf < 4; mf++) {
                uint32_t af[4];
                uint32_t aaddr = base + (mbase + mf * 16 + a_row) * GRPB + (kc + a_col) * 2;
                ldm_x4(af, aaddr);
#pragma unroll
                for (int nf = 0; nf < 4; nf++)
                    mma_f16(acc[mf][nf], af, bf + nf * 2);
            }
        }
        __syncthreads();
    }
#undef ISSUE_STAGE

    int grp = lid >> 2;
    int tg  = lid & 3;
    size_t ob = (size_t)b * COUT * NP + p0 + mbase;
#pragma unroll
    for (int nf = 0; nf < 4; nf++) {
        int col0 = n0 + nbase + nf * 8 + tg * 2;
        float bb0 = bu[col0];
        float bb1 = bu[col0 + 1];
        size_t o0 = ob + (size_t)col0 * NP;
        size_t o1 = ob + (size_t)(col0 + 1) * NP;
#pragma unroll
        for (int mf = 0; mf < 4; mf++) {
            int rr = mf * 16 + grp;
            out[o0 + rr]     = acc[mf][nf][0] + bb0;
            out[o1 + rr]     = acc[mf][nf][1] + bb1;
            out[o0 + rr + 8] = acc[mf][nf][2] + bb0;
            out[o1 + rr + 8] = acc[mf][nf][3] + bb1;
        }
    }
}

// ---------------- launch ----------------
extern "C" void kernel_launch(void* const* d_in, const int* in_sizes, int n_in,
                              void* d_out, int out_size) {
    const float* x     = (const float*)d_in[0];
    const float* W1    = (const float*)d_in[1];
    const float* b1    = (const float*)d_in[2];
    const float* W2    = (const float*)d_in[3];
    const float* b2    = (const float*)d_in[4];
    const float* Wu    = (const float*)d_in[5];
    const float* bu    = (const float*)d_in[6];
    const int*   gints = (const int*)d_in[7];
    const int*   roff  = (const int*)d_in[8];
    float* out = (float*)d_out;

    {
        dim3 blk(32, 8);
        dim3 grd(NP / 32, CIN / 32, NB);
        transpose_x_kernel<<<grd, blk>>>(x);
    }
    wu_prep_kernel<<<(COUT * KC / 8 + 255) / 256, 256>>>(Wu);
    w2t_prep_kernel<<<(27 * HID + 255) / 256, 256>>>(W2);
    mlp_kernel<<<NP / 8, 256>>>(W1, b1, b2);
    {
        int items = NB * NP * NK;
        weights_kernel<<<(items + 255) / 256, 256>>>(gints, roff);
    }
    build_a_kernel<<<(NB * NP * 16) / 256, 256>>>();
    cudaFuncSetAttribute(gemm2_kernel, cudaFuncAttributeMaxDynamicSharedMemorySize, SM_TOTAL);
    {
        dim3 grd(NB * NP / GBM, COUT / GBN);
        gemm2_kernel<<<grd, 256, SM_TOTAL>>>(bu, out);
    }
}

// round 15
// speedup vs baseline: 2.3915x; 1.4828x over previous
#include <cuda_runtime.h>
#include <cuda_fp16.h>
#include <math.h>
#include <stdint.h>

#define H_   48
#define W_   48
#define NP   2304        // H_*W_
#define NB   8
#define CIN  128
#define COUT 256
#define NK   9
#define HID  512
#define KC   1152        // NK*CIN
#define VS8  8

// GEMM tiling (fp16, m16n8k16)
#define GBM 128
#define GBN 128
#define GBK 64
#define GST 3            // pipeline stages
#define GRPB 144         // bytes per smem row: 64 fp16 = 128B + 16B pad (mod128==16 -> conflict-free)
#define STAGE_A (GBM * GRPB)             // 18432
#define STAGE_B (GBN * GRPB)             // 18432
#define STAGE_SZ (STAGE_A + STAGE_B)     // 36864
#define SM_TOTAL (GST * STAGE_SZ)        // 110592

// ---------------- scratch (static device globals; no allocation) ----------------
__device__ __half g_xt [NB * NP * CIN];        // x transposed to [b][p][c], fp16 (4.7MB)
__device__ float4 g_pk [NP * NK];              // mean_h, mean_w, sigma
__device__ float  g_wts[NB * NP * NK * VS8];
__device__ int    g_lin[NB * NP * NK * VS8];
__device__ __half g_wuh[COUT * KC];            // Wu fp16, [n][k] contiguous (0.6MB)
__device__ __half g_af [NB * NP * KC];         // gathered A, fp16 (42.5MB)
__device__ float  g_w2t[HID * 32];             // W2 transposed [n][o], zero-padded to 32

// ---------------- helpers ----------------
__device__ __forceinline__ uint32_t smem_u32(const void* p) {
    uint32_t a;
    asm("{ .reg .u64 t; cvta.to.shared.u64 t, %1; cvt.u32.u64 %0, t; }" : "=r"(a) : "l"(p));
    return a;
}
__device__ __forceinline__ void ldm_x4(uint32_t* r, uint32_t addr) {
    asm volatile("ldmatrix.sync.aligned.m8n8.x4.shared.b16 {%0,%1,%2,%3}, [%4];"
                 : "=r"(r[0]), "=r"(r[1]), "=r"(r[2]), "=r"(r[3]) : "r"(addr));
}
__device__ __forceinline__ void mma_f16(float* d, const uint32_t* a, const uint32_t* b) {
    asm volatile("mma.sync.aligned.m16n8k16.row.col.f32.f16.f16.f32 "
                 "{%0,%1,%2,%3}, {%4,%5,%6,%7}, {%8,%9}, {%0,%1,%2,%3};"
                 : "+f"(d[0]), "+f"(d[1]), "+f"(d[2]), "+f"(d[3])
                 : "r"(a[0]), "r"(a[1]), "r"(a[2]), "r"(a[3]), "r"(b[0]), "r"(b[1]));
}
__device__ __forceinline__ void cp_async16(uint32_t dst, const void* src) {
    asm volatile("cp.async.cg.shared.global [%0], [%1], 16;" :: "r"(dst), "l"(src) : "memory");
}
__device__ __forceinline__ void cp_commit() {
    asm volatile("cp.async.commit_group;" ::: "memory");
}

// ---------------- kernel 0a: transpose x (b,c,p) -> (b,p,c), fp32 -> fp16 ----------------
__global__ void transpose_x_kernel(const float* __restrict__ in) {
    __shared__ float tile[32][33];
    int b = blockIdx.z;
    const float* inb = in + (size_t)b * CIN * NP;
    __half* outb = g_xt + (size_t)b * NP * CIN;
    int c0 = blockIdx.x * 32;
    int r0 = blockIdx.y * 32;
    int tx = threadIdx.x, ty = threadIdx.y;
#pragma unroll
    for (int q = 0; q < 32; q += 8)
        tile[ty + q][tx] = inb[(r0 + ty + q) * NP + c0 + tx];
    __syncthreads();
#pragma unroll
    for (int q = 0; q < 32; q += 8)
        outb[(size_t)(c0 + ty + q) * CIN + r0 + tx] = __float2half_rn(tile[tx][ty + q]);
}

// ---------------- kernel 0b: Wu fp32 -> fp16 contiguous ----------------
__global__ void wu_prep_kernel(const float* __restrict__ wu) {
    int t = blockIdx.x * 256 + threadIdx.x;      // COUT*KC/8 = 36864
    if (t >= COUT * KC / 8) return;
    float4 v0 = ((const float4*)wu)[t * 2];
    float4 v1 = ((const float4*)wu)[t * 2 + 1];
    __half2 h[4];
    h[0] = __floats2half2_rn(v0.x, v0.y);
    h[1] = __floats2half2_rn(v0.z, v0.w);
    h[2] = __floats2half2_rn(v1.x, v1.y);
    h[3] = __floats2half2_rn(v1.z, v1.w);
    ((uint4*)g_wuh)[t] = *(uint4*)h;
}

// ---------------- kernel 0c: W2 [27][512] -> W2T [512][32] (zero padded) ----------------
__global__ void w2t_prep_kernel(const float* __restrict__ W2) {
    int t = blockIdx.x * 256 + threadIdx.x;      // 27*512 = 13824
    if (t >= 27 * HID) return;
    int o = t / HID;
    int n = t % HID;
    g_w2t[n * 32 + o] = W2[t];
}

// ---------------- kernel 1: per-pixel MLP (smem-staged, latency-free inner loop) ----------------
// block = 128 threads = 4 warps = 4 pixels. Lane o computes param o (o<27).
__global__ void __launch_bounds__(128) mlp_kernel(const float* __restrict__ W1,
                                                  const float* __restrict__ b1,
                                                  const float* __restrict__ b2) {
    __shared__ float4 s_w1b1[HID];        // (w1x, w1y, b1, 0)     8KB
    __shared__ float  s_w2t[HID * 28];    // [n][o<28]             56KB
    int tid = threadIdx.x;

    // ---- cooperative stage (high MLP: 4 + 28 independent wide loads/thread) ----
    for (int n = tid; n < HID; n += 128) {
        float2 w = ((const float2*)W1)[n];
        s_w1b1[n] = make_float4(w.x, w.y, b1[n], 0.0f);
    }
#pragma unroll
    for (int q = 0; q < 28; q++) {
        int idx4 = q * 128 + tid;              // 3584 float4 total
        int idx = idx4 * 4;                    // element in [n*28 + o]; 28%4==0 -> o%4==0
        int n = idx / 28, o = idx % 28;
        *(float4*)&s_w2t[idx] = *(const float4*)&g_w2t[n * 32 + o];
    }
    __syncthreads();

    int o  = tid & 31;
    int oc = (o < 27) ? o : 0;                 // lanes 27..31: safe dummy
    int p  = blockIdx.x * 4 + (tid >> 5);
    int i = p / W_, j = p % W_;
    float ri = (float)i / 47.0f;
    float cj = (float)j / 47.0f;

    float s0 = (o < 27) ? b2[o] : 0.0f;
    float s1 = 0.0f;
#pragma unroll 8
    for (int n = 0; n < HID; n += 2) {
        float4 wb0 = s_w1b1[n];
        float4 wb1 = s_w1b1[n + 1];
        float h0 = fmaxf(wb0.x * ri + wb0.y * cj + wb0.z, 0.0f);
        float h1 = fmaxf(wb1.x * ri + wb1.y * cj + wb1.z, 0.0f);
        s0 += h0 * s_w2t[n * 28 + oc];
        s1 += h1 * s_w2t[(n + 1) * 28 + oc];
    }
    float s = s0 + s1;

    // distribute params via shuffle; lane k (k<9) computes g_pk[p*9+k]
    float mrh = __shfl_sync(0xFFFFFFFFu, s, (o < 9) ? 2 * o : 0);
    float mrw = __shfl_sync(0xFFFFFFFFu, s, (o < 9) ? 2 * o + 1 : 0);
    float sr  = __shfl_sync(0xFFFFFFFFu, s, (o < 9) ? 18 + o : 0);
    if (o < NK) {
        float sch = ri * 0.9999f + 5e-5f;
        float scw = cj * 0.9999f + 5e-5f;
        float midh = logf(sch / (1.0f - sch));
        float midw = logf(scw / (1.0f - scw));
        float mh = 47.0f / (1.0f + expf(-(midh + 0.1f * mrh)));
        float mw = 47.0f / (1.0f + expf(-(midw + 0.1f * mrw)));
        float sp = sr + 2.0f;
        float spl = (sp > 20.0f) ? sp : log1pf(expf(sp));
        float sig = (spl + 0.05f) * (48.0f * 0.05f);
        g_pk[p * NK + o] = make_float4(mh, mw, sig, 0.0f);
    }
}

// ---------------- kernel 2: candidate cells, dedup, normalized weights ----------------
__global__ void weights_kernel(const int* __restrict__ gints, const int* __restrict__ roff) {
    int t = blockIdx.x * 256 + threadIdx.x;
    if (t >= NB * NP * NK) return;
    int k = t % NK;
    int p = (t / NK) % NP;
    float4 pk = g_pk[p * NK + k];
    float mh = pk.x, mw = pk.y, sig = pk.z;
    int flh = (int)floorf(mh);
    int flw = (int)floorf(mw);

    int r[8], c[8];
    r[0] = flh;     c[0] = flw;
    r[1] = flh;     c[1] = flw + 1;
    r[2] = flh + 1; c[2] = flw;
    r[3] = flh + 1; c[3] = flw + 1;
    int4 g  = *(const int4*)(gints + (size_t)t * 4);
    r[4] = g.x;  c[4] = g.y;
    r[5] = g.z;  c[5] = g.w;
    int4 ro = *(const int4*)(roff + (size_t)t * 4);
    r[6] = flh + ro.x - 6; c[6] = flw + ro.y - 6;
    r[7] = flh + ro.z - 6; c[7] = flw + ro.w - 6;
#pragma unroll
    for (int v = 0; v < 8; v++) {
        r[v] = (r[v] + 48) % 48;
        c[v] = (c[v] + 48) % 48;
    }

    float inv_s = 1.0f / sig;
    float pr[8];
    float sum = 0.0f;
#pragma unroll
    for (int v = 0; v < 8; v++) {
        bool dup = false;
#pragma unroll
        for (int u = 0; u < 8; u++)
            if (u < v && r[v] == r[u] && c[v] == c[u]) dup = true;
        float dh = ((float)r[v] - mh) * inv_s;
        float dw = ((float)c[v] - mw) * inv_s;
        float e = dup ? 0.0f : expf(-0.5f * (dh * dh + dw * dw));
        pr[v] = e;
        sum += e;
    }
    float inv = 1.0f / sum;
    float wv[8];
    int   lv[8];
#pragma unroll
    for (int v = 0; v < 8; v++) {
        wv[v] = pr[v] * inv;
        lv[v] = r[v] * 48 + c[v];
    }
    *(float4*)(g_wts + (size_t)t * 8)     = make_float4(wv[0], wv[1], wv[2], wv[3]);
    *(float4*)(g_wts + (size_t)t * 8 + 4) = make_float4(wv[4], wv[5], wv[6], wv[7]);
    *(int4*)(g_lin + (size_t)t * 8)       = make_int4(lv[0], lv[1], lv[2], lv[3]);
    *(int4*)(g_lin + (size_t)t * 8 + 4)   = make_int4(lv[4], lv[5], lv[6], lv[7]);
}

// ---------------- kernel 3a: build A (fp16 gather + fp32 weight + fp16 store) ----------------
__global__ void build_a_kernel() {
    int t = blockIdx.x * 256 + threadIdx.x;      // NB*NP*16 = 294912
    int c8 = t & 15;
    int bp = t >> 4;
    int b  = bp / NP;
    const __half* xtb = g_xt + (size_t)b * NP * CIN;
    __half* arow = g_af + (size_t)bp * KC;

    for (int kk = 0; kk < NK; kk++) {
        int wb = (bp * NK + kk) * VS8;
        float4 w0 = *(const float4*)(g_wts + wb);
        float4 w1 = *(const float4*)(g_wts + wb + 4);
        int4   l0 = *(const int4*)(g_lin + wb);
        int4   l1 = *(const int4*)(g_lin + wb + 4);
        float a[8];
#pragma unroll
        for (int q = 0; q < 8; q++) a[q] = 0.0f;
#define GATH(WV, LV)                                                              \
        {                                                                         \
            uint4 rv = *(const uint4*)(xtb + (size_t)(LV) * CIN + c8 * 8);        \
            const __half2* h2 = (const __half2*)&rv;                              \
            _Pragma("unroll")                                                     \
            for (int q = 0; q < 4; q++) {                                         \
                float2 f = __half22float2(h2[q]);                                 \
                a[q * 2]     += (WV) * f.x;                                       \
                a[q * 2 + 1] += (WV) * f.y;                                       \
            }                                                                     \
        }
        GATH(w0.x, l0.x) GATH(w0.y, l0.y) GATH(w0.z, l0.z) GATH(w0.w, l0.w)
        GATH(w1.x, l1.x) GATH(w1.y, l1.y) GATH(w1.z, l1.z) GATH(w1.w, l1.w)
#undef GATH
        __half2 o[4];
#pragma unroll
        for (int q = 0; q < 4; q++)
            o[q] = __floats2half2_rn(a[q * 2], a[q * 2 + 1]);
        *(uint4*)(arow + kk * CIN + c8 * 8) = *(uint4*)o;
    }
}

// ---------------- kernel 3b: pipelined fp16 GEMM: out = A @ Wu^T + bu ----------------
__global__ void __launch_bounds__(256, 2) gemm2_kernel(const float* __restrict__ bu,
                                                       float* __restrict__ out) {
    extern __shared__ char smem[];
    uint32_t sb = smem_u32(smem);
    int tid = threadIdx.x;
    int wid = tid >> 5;
    int lid = tid & 31;

    int m0 = blockIdx.x * GBM;
    int n0 = blockIdx.y * GBN;
    int b  = m0 / NP;
    int p0 = m0 % NP;

    int wm = wid & 1;
    int wn = wid >> 1;
    int mbase = wm * 64;
    int nbase = wn * 32;

    int a_row = (lid & 15);
    int a_col = (lid >> 4) * 8;
    int b_row = (lid & 7) + ((lid >> 4) & 1) * 8;
    int b_col = ((lid >> 3) & 1) * 8;

    float acc[4][4][4];
#pragma unroll
    for (int i = 0; i < 4; i++)
#pragma unroll
        for (int j = 0; j < 4; j++)
#pragma unroll
            for (int q = 0; q < 4; q++) acc[i][j][q] = 0.0f;

    const __half* abase = g_af + (size_t)m0 * KC;
    const __half* bbase = g_wuh + (size_t)n0 * KC;

#define ISSUE_STAGE(KT_IDX)                                                         \
    {                                                                               \
        int st = (KT_IDX) % GST;                                                    \
        uint32_t da = sb + st * STAGE_SZ;                                           \
        uint32_t db = da + STAGE_A;                                                 \
        const __half* sa = abase + (KT_IDX) * GBK;                                  \
        const __half* sg = bbase + (KT_IDX) * GBK;                                  \
        _Pragma("unroll")                                                           \
        for (int q = 0; q < 4; q++) {                                               \
            int idx = q * 256 + tid;                                                \
            int row = idx >> 3, c16 = idx & 7;                                      \
            cp_async16(da + row * GRPB + c16 * 16, sa + (size_t)row * KC + c16 * 8);\
            cp_async16(db + row * GRPB + c16 * 16, sg + (size_t)row * KC + c16 * 8);\
        }                                                                           \
        cp_commit();                                                                \
    }

    ISSUE_STAGE(0)
    ISSUE_STAGE(1)

    const int NKT = KC / GBK;    // 18
    for (int kt = 0; kt < NKT; kt++) {
        if (kt + GST - 1 < NKT) {
            asm volatile("cp.async.wait_group %0;" :: "n"(GST - 2));
        } else {
            asm volatile("cp.async.wait_group 0;" ::: "memory");
        }
        __syncthreads();
        if (kt + GST - 1 < NKT) ISSUE_STAGE(kt + GST - 1)

        uint32_t base = sb + (kt % GST) * STAGE_SZ;
#pragma unroll
        for (int ks = 0; ks < 4; ks++) {
            int kc = ks * 16;
            uint32_t bf[8];
            uint32_t addr0 = base + STAGE_A + (nbase + b_row) * GRPB + (kc + b_col) * 2;
            uint32_t addr1 = base + STAGE_A + (nbase + 16 + b_row) * GRPB + (kc + b_col) * 2;
            ldm_x4(bf, addr0);
            ldm_x4(bf + 4, addr1);
#pragma unroll
            for (int mf = 0; mf < 4; mf++) {
                uint32_t af[4];
                uint32_t aaddr = base + (mbase + mf * 16 + a_row) * GRPB + (kc + a_col) * 2;
                ldm_x4(af, aaddr);
#pragma unroll
                for (int nf = 0; nf < 4; nf++)
                    mma_f16(acc[mf][nf], af, bf + nf * 2);
            }
        }
        __syncthreads();
    }
#undef ISSUE_STAGE

    int grp = lid >> 2;
    int tg  = lid & 3;
    size_t ob = (size_t)b * COUT * NP + p0 + mbase;
#pragma unroll
    for (int nf = 0; nf < 4; nf++) {
        int col0 = n0 + nbase + nf * 8 + tg * 2;
        float bb0 = bu[col0];
        float bb1 = bu[col0 + 1];
        size_t o0 = ob + (size_t)col0 * NP;
        size_t o1 = ob + (size_t)(col0 + 1) * NP;
#pragma unroll
        for (int mf = 0; mf < 4; mf++) {
            int rr = mf * 16 + grp;
            out[o0 + rr]     = acc[mf][nf][0] + bb0;
            out[o1 + rr]     = acc[mf][nf][1] + bb1;
            out[o0 + rr + 8] = acc[mf][nf][2] + bb0;
            out[o1 + rr + 8] = acc[mf][nf][3] + bb1;
        }
    }
}

// ---------------- launch ----------------
extern "C" void kernel_launch(void* const* d_in, const int* in_sizes, int n_in,
                              void* d_out, int out_size) {
    const float* x     = (const float*)d_in[0];
    const float* W1    = (const float*)d_in[1];
    const float* b1    = (const float*)d_in[2];
    const float* W2    = (const float*)d_in[3];
    const float* b2    = (const float*)d_in[4];
    const float* Wu    = (const float*)d_in[5];
    const float* bu    = (const float*)d_in[6];
    const int*   gints = (const int*)d_in[7];
    const int*   roff  = (const int*)d_in[8];
    float* out = (float*)d_out;

    {
        dim3 blk(32, 8);
        dim3 grd(NP / 32, CIN / 32, NB);
        transpose_x_kernel<<<grd, blk>>>(x);
    }
    wu_prep_kernel<<<(COUT * KC / 8 + 255) / 256, 256>>>(Wu);
    w2t_prep_kernel<<<(27 * HID + 255) / 256, 256>>>(W2);
    mlp_kernel<<<NP / 4, 128>>>(W1, b1, b2);
    {
        int items = NB * NP * NK;
        weights_kernel<<<(items + 255) / 256, 256>>>(gints, roff);
    }
    build_a_kernel<<<(NB * NP * 16) / 256, 256>>>();
    cudaFuncSetAttribute(gemm2_kernel, cudaFuncAttributeMaxDynamicSharedMemorySize, SM_TOTAL);
    {
        dim3 grd(NB * NP / GBM, COUT / GBN);
        gemm2_kernel<<<grd, 256, SM_TOTAL>>>(bu, out);
    }
}